// round 15
// baseline (speedup 1.0000x reference)
#include <cuda_runtime.h>

// FastGuidedFilterColor — bit-faithful to JAX reference
// (XLA ReduceWindowRewriter blocked scan, base_length B=16):
//   S_j = serial left-fold within 16-elem block; C_k = serial fold of totals;
//   cs[16k+j] = round(C_k + S_j). Non-FMA intrinsics, IEEE divides.
// Bilinear resize: separable clamped lerp, exact dyadic weights.

#define NB 8
#define NC 3
#define LH 256
#define LW 256
#define HH 1024
#define HW 1024
#define EPSV 1e-8f
#define NPL 21
#define PL (LH * LW)

#define SMSTRIDE 20   // apply: 80B column stride -> conflict-free LDS128

__device__ float g_box[NB * NPL * PL];    // vertical-scan output only
__device__ float g_ab2[NB * PL * 12];     // pixel-major A/b

__device__ __constant__ int cI1[6] = {0, 0, 0, 1, 1, 2};
__device__ __constant__ int cI2[6] = {0, 1, 2, 1, 2, 2};

// ---------------------------------------------------------------------------
// Kernel 1: vertical blocked scan + diff. Block = (b, plane, 32-col slice),
// float2 per thread (low register pressure). 16 fl2-groups x 16 y-blocks.
// ---------------------------------------------------------------------------
__global__ void __launch_bounds__(256) gf_box_v(
    const float* __restrict__ lrx,
    const float* __restrict__ lry)
{
    int blk = blockIdx.x;            // (b*NPL + plane)*8 + slice
    int slice = blk & 7;
    int ip = blk >> 3;
    int plane = ip % NPL;
    int b = ip / NPL;
    int tid = threadIdx.x;
    int xl = tid & 15;
    int xg = xl + slice * 16;        // float2 group 0..127
    int kb = tid >> 4;               // y-block 0..15

    float* pp = g_box + ((size_t)b * NPL + plane) * PL;

    __shared__ float2 Tsm[16][16];
    __shared__ float2 i13s[16][16];
    __shared__ float2 i14s[16][16];

    const float2* pA2;
    const float2* pB2 = nullptr;
    if (plane < 3) {
        pA2 = (const float2*)(lrx + ((size_t)b * NC + plane) * PL) + xg;
    } else if (plane < 6) {
        pA2 = (const float2*)(lry + ((size_t)b * NC + (plane - 3)) * PL) + xg;
    } else if (plane < 12) {
        int k = plane - 6;
        pA2 = (const float2*)(lrx + ((size_t)b * NC + cI1[k]) * PL) + xg;
        pB2 = (const float2*)(lrx + ((size_t)b * NC + cI2[k]) * PL) + xg;
    } else {
        int q = plane - 12;
        pA2 = (const float2*)(lrx + ((size_t)b * NC + (q % 3)) * PL) + xg;
        pB2 = (const float2*)(lry + ((size_t)b * NC + (q / 3)) * PL) + xg;
    }

    // ---- pass A: block totals + partials ----
    {
        float2 inner = make_float2(0.f, 0.f);
        float2 i13 = inner, i14 = inner;
        #pragma unroll
        for (int j = 0; j < 16; j++) {
            int t = kb * 16 + j;
            float2 v = pA2[t * 128];
            if (pB2) {
                float2 w = pB2[t * 128];
                v.x = __fmul_rn(v.x, w.x); v.y = __fmul_rn(v.y, w.y);
            }
            inner.x = __fadd_rn(inner.x, v.x);
            inner.y = __fadd_rn(inner.y, v.y);
            if (j == 13) i13 = inner;
            if (j == 14) i14 = inner;
        }
        Tsm[kb][xl] = inner;
        i13s[kb][xl] = i13;
        i14s[kb][xl] = i14;
    }
    __syncthreads();

    // ---- pass B: carry fold + rescan + vertical diff ----
    {
        float2 C = make_float2(0.f, 0.f);
        float2 Cp = C;
        for (int jj = 0; jj < kb; jj++) {
            Cp = C;
            float2 T = Tsm[jj][xl];
            C.x = __fadd_rn(C.x, T.x); C.y = __fadd_rn(C.y, T.y);
        }
        float2 h1 = make_float2(0.f, 0.f), h2 = h1, h3 = h1;
        if (kb > 0) {
            float2 p13 = i13s[kb - 1][xl];
            float2 p14 = i14s[kb - 1][xl];
            float2 Tp  = Tsm[kb - 1][xl];
            h3.x = __fadd_rn(Cp.x, p13.x); h3.y = __fadd_rn(Cp.y, p13.y);
            h2.x = __fadd_rn(Cp.x, p14.x); h2.y = __fadd_rn(Cp.y, p14.y);
            h1.x = __fadd_rn(Cp.x, Tp.x);  h1.y = __fadd_rn(Cp.y, Tp.y);
        }
        float2 inner = make_float2(0.f, 0.f);
        float2* po = (float2*)pp + xg;
        #pragma unroll
        for (int j = 0; j < 16; j++) {
            int t = kb * 16 + j;
            float2 v = pA2[t * 128];
            if (pB2) {
                float2 w = pB2[t * 128];
                v.x = __fmul_rn(v.x, w.x); v.y = __fmul_rn(v.y, w.y);
            }
            inner.x = __fadd_rn(inner.x, v.x);
            inner.y = __fadd_rn(inner.y, v.y);
            float2 cs;
            cs.x = __fadd_rn(C.x, inner.x); cs.y = __fadd_rn(C.y, inner.y);
            if (t >= 1) {
                float2 ov;
                if (t >= 3) {
                    ov.x = __fsub_rn(cs.x, h3.x); ov.y = __fsub_rn(cs.y, h3.y);
                } else {
                    ov = cs;
                }
                po[(t - 1) * 128] = ov;
            }
            h3 = h2; h2 = h1; h1 = cs;
        }
        if (kb == 15) {
            float2 ov;
            ov.x = __fsub_rn(h1.x, h3.x); ov.y = __fsub_rn(h1.y, h3.y);
            po[(LH - 1) * 128] = ov;
        }
    }
}

// ---------------------------------------------------------------------------
// Kernel 2 (fused): horizontal scan + diff + covariance solve.
// Block = one (b, row); transposed stride-17 smem staging; thread = pixel.
// ---------------------------------------------------------------------------
__global__ void __launch_bounds__(256) gf_hsolve()
{
    int y = blockIdx.x & 255;
    int b = blockIdx.x >> 8;
    int tid = threadIdx.x;
    int wid = tid >> 5;
    int lane = tid & 31;
    int half = (lane >> 4) & 1;
    int hw = tid >> 4;          // half-warp id 0..15
    int k = lane & 15;          // 16-col block index
    int hb = half << 4;

    __shared__ float smbox[NPL][272];   // [plane][j*17 + k]

    #pragma unroll
    for (int pb = 0; pb < 2; pb++) {
        if (pb == 1 && wid > 2) break;       // whole warps 3..7 skip pass 2
        int praw = pb * 16 + hw;
        int plane = praw < NPL ? praw : NPL - 1;   // dummy half-warp clamps
        const float4* rv = (const float4*)(g_box +
            ((size_t)b * NPL + plane) * PL + (size_t)y * LW) + k * 4;
        float4 a0 = rv[0], a1 = rv[1], a2 = rv[2], a3 = rv[3];
        float cs[16] = {a0.x, a0.y, a0.z, a0.w,
                        a1.x, a1.y, a1.z, a1.w,
                        a2.x, a2.y, a2.z, a2.w,
                        a3.x, a3.y, a3.z, a3.w};
        #pragma unroll
        for (int j = 1; j < 16; j++) cs[j] = __fadd_rn(cs[j - 1], cs[j]);

        float T = cs[15];
        float carry = 0.f;
        #pragma unroll
        for (int i = 0; i < 16; i++) {
            float Ti = __shfl_sync(0xFFFFFFFFu, T, hb | i);
            if (i < k) carry = __fadd_rn(carry, Ti);   // serial fold order
        }
        #pragma unroll
        for (int j = 0; j < 16; j++) cs[j] = __fadd_rn(carry, cs[j]);

        float csp14 = __shfl_sync(0xFFFFFFFFu, cs[14], hb | ((k - 1) & 15));
        float csp15 = __shfl_sync(0xFFFFFFFFu, cs[15], hb | ((k - 1) & 15));
        float csn0  = __shfl_sync(0xFFFFFFFFu, cs[0],  hb | ((k + 1) & 15));

        float o[16];
        if (k == 0) { o[0] = cs[1]; o[1] = cs[2]; }
        else {
            o[0] = __fsub_rn(cs[1], csp14);
            o[1] = __fsub_rn(cs[2], csp15);
        }
        #pragma unroll
        for (int j = 2; j < 15; j++) o[j] = __fsub_rn(cs[j + 1], cs[j - 2]);
        o[15] = (k == 15) ? __fsub_rn(cs[15], cs[13])
                          : __fsub_rn(csn0, cs[13]);

        if (praw < NPL) {
            #pragma unroll
            for (int j = 0; j < 16; j++) smbox[plane][j * 17 + k] = o[j];
        }
    }
    __syncthreads();

    // ---- solve for pixel (y, x = tid) ----
    int x = tid;
    int loc = (x & 15) * 17 + (x >> 4);

    int y0 = max(0, y - 1), y1 = min(LH - 1, y + 1);
    int x0 = max(0, x - 1), x1 = min(LW - 1, x + 1);
    float n = (float)((y1 - y0 + 1) * (x1 - x0 + 1));

    float mx[3], my[3];
    #pragma unroll
    for (int c = 0; c < 3; c++) mx[c] = __fdiv_rn(smbox[c][loc], n);
    #pragma unroll
    for (int c = 0; c < 3; c++) my[c] = __fdiv_rn(smbox[3 + c][loc], n);

    float v[6];
    {
        const int i1[6] = {0, 0, 0, 1, 1, 2};
        const int i2[6] = {0, 1, 2, 1, 2, 2};
        #pragma unroll
        for (int kk = 0; kk < 6; kk++) {
            float d = __fdiv_rn(smbox[6 + kk][loc], n);
            float mm = __fmul_rn(mx[i1[kk]], mx[i2[kk]]);
            v[kk] = __fadd_rn(__fsub_rn(d, mm), EPSV);
        }
    }

    float c0 = __fsub_rn(__fmul_rn(v[3], v[5]), __fmul_rn(v[4], v[4]));
    float c1 = __fsub_rn(__fmul_rn(v[4], v[2]), __fmul_rn(v[1], v[5]));
    float c2 = __fsub_rn(__fmul_rn(v[1], v[4]), __fmul_rn(v[3], v[2]));
    float c3 = __fsub_rn(__fmul_rn(v[0], v[5]), __fmul_rn(v[2], v[2]));
    float c4 = __fsub_rn(__fmul_rn(v[2], v[1]), __fmul_rn(v[0], v[4]));
    float c5 = __fsub_rn(__fmul_rn(v[0], v[3]), __fmul_rn(v[1], v[1]));

    float det = __fadd_rn(__fadd_rn(__fmul_rn(c0, v[0]), __fmul_rn(c1, v[1])),
                          __fmul_rn(c2, v[2]));
    c0 = __fdiv_rn(c0, det);
    c1 = __fdiv_rn(c1, det);
    c2 = __fdiv_rn(c2, det);
    c3 = __fdiv_rn(c3, det);
    c4 = __fdiv_rn(c4, det);
    c5 = __fdiv_rn(c5, det);

    float4* o4 = (float4*)(g_ab2 + ((size_t)b * PL + (size_t)y * LW + x) * 12);

    #pragma unroll
    for (int i = 0; i < 3; i++) {
        float cov[3];
        #pragma unroll
        for (int c = 0; c < 3; c++) {
            float d = __fdiv_rn(smbox[12 + i * 3 + c][loc], n);
            cov[c] = __fsub_rn(d, __fmul_rn(mx[c], my[i]));
        }
        float A0 = __fadd_rn(__fadd_rn(__fmul_rn(c0, cov[0]), __fmul_rn(c1, cov[1])),
                             __fmul_rn(c2, cov[2]));
        float A1 = __fadd_rn(__fadd_rn(__fmul_rn(c1, cov[0]), __fmul_rn(c3, cov[1])),
                             __fmul_rn(c4, cov[2]));
        float A2 = __fadd_rn(__fadd_rn(__fmul_rn(c2, cov[0]), __fmul_rn(c4, cov[1])),
                             __fmul_rn(c5, cov[2]));
        float s = __fadd_rn(__fadd_rn(__fmul_rn(A0, mx[0]), __fmul_rn(A1, mx[1])),
                            __fmul_rn(A2, mx[2]));
        float bb = __fsub_rn(my[i], s);
        o4[i] = make_float4(A0, A1, A2, bb);
    }
}

// ---------------------------------------------------------------------------
// Kernel 3: bilinear upsample + apply. Block = one output row (b, y).
// Interior threads use compile-time dyadic x-weights (bit-identical).
// ---------------------------------------------------------------------------
__global__ void __launch_bounds__(256, 4) gf_apply(
    const float* __restrict__ hrx,
    float* __restrict__ out)
{
    int y = blockIdx.x & (HH - 1);
    int b = blockIdx.x >> 10;
    int t = threadIdx.x;               // lr column / output group

    __shared__ float smrow[256 * SMSTRIDE];   // 20 KB

    float fy = (y + 0.5f) * 0.25f - 0.5f;
    fy = fminf(fmaxf(fy, 0.0f), (float)(LH - 1));
    int iy0 = (int)fy;
    float wy = fy - (float)iy0;
    int iy1 = min(iy0 + 1, LH - 1);
    float wy0 = 1.0f - wy, wy1 = wy;

    // ---- Phase 1: y-lerp column t into smem ----
    {
        const float4* ab = (const float4*)g_ab2 + (size_t)b * PL * 3;
        const float4* top = ab + ((size_t)iy0 * LW + t) * 3;
        const float4* bot = ab + ((size_t)iy1 * LW + t) * 3;
        float4* dst = (float4*)(smrow + t * SMSTRIDE);
        #pragma unroll
        for (int q = 0; q < 3; q++) {
            float4 tt = top[q], bo = bot[q];
            float4 r;
            r.x = __fadd_rn(__fmul_rn(tt.x, wy0), __fmul_rn(bo.x, wy1));
            r.y = __fadd_rn(__fmul_rn(tt.y, wy0), __fmul_rn(bo.y, wy1));
            r.z = __fadd_rn(__fmul_rn(tt.z, wy0), __fmul_rn(bo.z, wy1));
            r.w = __fadd_rn(__fmul_rn(tt.w, wy0), __fmul_rn(bo.w, wy1));
            dst[q] = r;
        }
    }
    __syncthreads();

    // ---- Phase 2: x-lerp + apply for x = 4t..4t+3 ----
    const float4* pa = (const float4*)(smrow + max(t - 1, 0) * SMSTRIDE);
    const float4* pb = (const float4*)(smrow + t * SMSTRIDE);
    const float4* pc = (const float4*)(smrow + min(t + 1, LW - 1) * SMSTRIDE);

    size_t hbase = (((size_t)b * 3) * HH + y) * HW + ((size_t)t << 2);
    const size_t hpl = (size_t)HH * HW;
    float4 hq0 = *(const float4*)(hrx + hbase);
    float4 hq1 = *(const float4*)(hrx + hbase + hpl);
    float4 hq2 = *(const float4*)(hrx + hbase + 2 * hpl);
    float hx0[4] = {hq0.x, hq0.y, hq0.z, hq0.w};
    float hx1[4] = {hq1.x, hq1.y, hq1.z, hq1.w};
    float hx2[4] = {hq2.x, hq2.y, hq2.z, hq2.w};

    float* outp = out + hbase;

    if (t > 0 && t < LW - 1) {
        // interior: fixed dyadic weights, fixed A/B/C pattern
        #pragma unroll
        for (int q = 0; q < 3; q++) {
            float4 A = pa[q], B = pb[q], C = pc[q];
            float4 vd[4];
            #define XLERP(dst, l, r, W0, W1)                                   \
                dst.x = __fadd_rn(__fmul_rn(l.x, W0), __fmul_rn(r.x, W1));     \
                dst.y = __fadd_rn(__fmul_rn(l.y, W0), __fmul_rn(r.y, W1));     \
                dst.z = __fadd_rn(__fmul_rn(l.z, W0), __fmul_rn(r.z, W1));     \
                dst.w = __fadd_rn(__fmul_rn(l.w, W0), __fmul_rn(r.w, W1));
            XLERP(vd[0], A, B, 0.375f, 0.625f)
            XLERP(vd[1], A, B, 0.125f, 0.875f)
            XLERP(vd[2], B, C, 0.875f, 0.125f)
            XLERP(vd[3], B, C, 0.625f, 0.375f)
            #undef XLERP
            float o[4];
            #pragma unroll
            for (int d = 0; d < 4; d++) {
                float s = __fadd_rn(__fadd_rn(__fmul_rn(vd[d].x, hx0[d]),
                                              __fmul_rn(vd[d].y, hx1[d])),
                                    __fmul_rn(vd[d].z, hx2[d]));
                o[d] = __fadd_rn(s, vd[d].w);
            }
            *(float4*)(outp + q * hpl) = make_float4(o[0], o[1], o[2], o[3]);
        }
    } else {
        // edge: general clamped path (unchanged arithmetic)
        float w0[4], w1[4];
        int s0[4], s1[4];
        #pragma unroll
        for (int d = 0; d < 4; d++) {
            float fx = ((float)(4 * t + d) + 0.5f) * 0.25f - 0.5f;
            fx = fminf(fmaxf(fx, 0.0f), (float)(LW - 1));
            int ix0 = (int)fx;
            float wx = fx - (float)ix0;
            int ix1 = min(ix0 + 1, LW - 1);
            w1[d] = wx;
            w0[d] = 1.0f - wx;
            s0[d] = ix0 - t + 1;
            s1[d] = ix1 - t + 1;
        }
        #pragma unroll
        for (int q = 0; q < 3; q++) {
            float4 A = pa[q], B = pb[q], C = pc[q];
            float o[4];
            #pragma unroll
            for (int d = 0; d < 4; d++) {
                float4 l = (s0[d] == 0) ? A : B;
                float4 r = (s1[d] == 2) ? C : B;
                float v0 = __fadd_rn(__fmul_rn(l.x, w0[d]), __fmul_rn(r.x, w1[d]));
                float v1 = __fadd_rn(__fmul_rn(l.y, w0[d]), __fmul_rn(r.y, w1[d]));
                float v2 = __fadd_rn(__fmul_rn(l.z, w0[d]), __fmul_rn(r.z, w1[d]));
                float v3 = __fadd_rn(__fmul_rn(l.w, w0[d]), __fmul_rn(r.w, w1[d]));
                float s = __fadd_rn(__fadd_rn(__fmul_rn(v0, hx0[d]),
                                              __fmul_rn(v1, hx1[d])),
                                    __fmul_rn(v2, hx2[d]));
                o[d] = __fadd_rn(s, v3);
            }
            *(float4*)(outp + q * hpl) = make_float4(o[0], o[1], o[2], o[3]);
        }
    }
}

extern "C" void kernel_launch(void* const* d_in, const int* in_sizes, int n_in,
                              void* d_out, int out_size)
{
    const float* lrx = (const float*)d_in[0];
    const float* lry = (const float*)d_in[1];
    const float* hrx = (const float*)d_in[2];
    float* out = (float*)d_out;

    gf_box_v<<<NB * NPL * 8, 256>>>(lrx, lry);       // 1344 blocks
    gf_hsolve<<<NB * LH, 256>>>();                   // 2048 blocks
    gf_apply<<<NB * HH, 256>>>(hrx, out);            // 8192 blocks
}

// round 16
// speedup vs baseline: 1.1854x; 1.1854x over previous
#include <cuda_runtime.h>

// FastGuidedFilterColor — bit-faithful to JAX reference
// (XLA ReduceWindowRewriter blocked scan, base_length B=16):
//   S_j = serial left-fold within 16-elem block; C_k = serial fold of totals;
//   cs[16k+j] = round(C_k + S_j). Non-FMA intrinsics, IEEE divides.
// Bilinear resize: separable clamped lerp, exact dyadic weights.

#define NB 8
#define NC 3
#define LH 256
#define LW 256
#define HH 1024
#define HW 1024
#define EPSV 1e-8f
#define NPL 21
#define PL (LH * LW)

#define SMSTRIDE 20   // apply: 80B column stride -> conflict-free LDS128

__device__ float g_box[NB * NPL * PL];    // vertical-scan output only
__device__ float g_ab2[NB * PL * 12];     // pixel-major A/b

__device__ __constant__ int cI1[6] = {0, 0, 0, 1, 1, 2};
__device__ __constant__ int cI2[6] = {0, 1, 2, 1, 2, 2};

// ---------------------------------------------------------------------------
// Kernel 1: vertical blocked scan + diff. Block = (b, plane, 64-col slice),
// float4 per thread (R14 proven version). 16 fl4-groups x 16 y-blocks.
// ---------------------------------------------------------------------------
__global__ void __launch_bounds__(256) gf_box_v(
    const float* __restrict__ lrx,
    const float* __restrict__ lry)
{
    int blk = blockIdx.x;            // (b*NPL + plane)*4 + slice
    int slice = blk & 3;
    int ip = blk >> 2;
    int plane = ip % NPL;
    int b = ip / NPL;
    int tid = threadIdx.x;
    int xg = (tid & 15) + slice * 16;   // float4 column group 0..63
    int kb = tid >> 4;                  // y-block 0..15

    float* pp = g_box + ((size_t)b * NPL + plane) * PL;

    __shared__ float4 Tsm[16][16];
    __shared__ float4 i13s[16][16];
    __shared__ float4 i14s[16][16];

    const float4* pA4;
    const float4* pB4 = nullptr;
    if (plane < 3) {
        pA4 = (const float4*)(lrx + ((size_t)b * NC + plane) * PL) + xg;
    } else if (plane < 6) {
        pA4 = (const float4*)(lry + ((size_t)b * NC + (plane - 3)) * PL) + xg;
    } else if (plane < 12) {
        int k = plane - 6;
        pA4 = (const float4*)(lrx + ((size_t)b * NC + cI1[k]) * PL) + xg;
        pB4 = (const float4*)(lrx + ((size_t)b * NC + cI2[k]) * PL) + xg;
    } else {
        int q = plane - 12;
        pA4 = (const float4*)(lrx + ((size_t)b * NC + (q % 3)) * PL) + xg;
        pB4 = (const float4*)(lry + ((size_t)b * NC + (q / 3)) * PL) + xg;
    }

    // ---- pass A ----
    {
        float4 inner = make_float4(0.f, 0.f, 0.f, 0.f);
        float4 i13 = inner, i14 = inner;
        #pragma unroll
        for (int j = 0; j < 16; j++) {
            int t = kb * 16 + j;
            float4 v = pA4[t * 64];
            if (pB4) {
                float4 w = pB4[t * 64];
                v.x = __fmul_rn(v.x, w.x); v.y = __fmul_rn(v.y, w.y);
                v.z = __fmul_rn(v.z, w.z); v.w = __fmul_rn(v.w, w.w);
            }
            inner.x = __fadd_rn(inner.x, v.x);
            inner.y = __fadd_rn(inner.y, v.y);
            inner.z = __fadd_rn(inner.z, v.z);
            inner.w = __fadd_rn(inner.w, v.w);
            if (j == 13) i13 = inner;
            if (j == 14) i14 = inner;
        }
        Tsm[kb][tid & 15] = inner;
        i13s[kb][tid & 15] = i13;
        i14s[kb][tid & 15] = i14;
    }
    __syncthreads();

    // ---- pass B ----
    {
        int xl = tid & 15;
        float4 C = make_float4(0.f, 0.f, 0.f, 0.f);
        float4 Cp = C;
        for (int jj = 0; jj < kb; jj++) {
            Cp = C;
            float4 T = Tsm[jj][xl];
            C.x = __fadd_rn(C.x, T.x); C.y = __fadd_rn(C.y, T.y);
            C.z = __fadd_rn(C.z, T.z); C.w = __fadd_rn(C.w, T.w);
        }
        float4 h1 = make_float4(0.f, 0.f, 0.f, 0.f), h2 = h1, h3 = h1;
        if (kb > 0) {
            float4 p13 = i13s[kb - 1][xl];
            float4 p14 = i14s[kb - 1][xl];
            float4 Tp  = Tsm[kb - 1][xl];
            h3.x = __fadd_rn(Cp.x, p13.x); h3.y = __fadd_rn(Cp.y, p13.y);
            h3.z = __fadd_rn(Cp.z, p13.z); h3.w = __fadd_rn(Cp.w, p13.w);
            h2.x = __fadd_rn(Cp.x, p14.x); h2.y = __fadd_rn(Cp.y, p14.y);
            h2.z = __fadd_rn(Cp.z, p14.z); h2.w = __fadd_rn(Cp.w, p14.w);
            h1.x = __fadd_rn(Cp.x, Tp.x);  h1.y = __fadd_rn(Cp.y, Tp.y);
            h1.z = __fadd_rn(Cp.z, Tp.z);  h1.w = __fadd_rn(Cp.w, Tp.w);
        }
        float4 inner = make_float4(0.f, 0.f, 0.f, 0.f);
        float4* po = (float4*)pp + xg;
        #pragma unroll
        for (int j = 0; j < 16; j++) {
            int t = kb * 16 + j;
            float4 v = pA4[t * 64];
            if (pB4) {
                float4 w = pB4[t * 64];
                v.x = __fmul_rn(v.x, w.x); v.y = __fmul_rn(v.y, w.y);
                v.z = __fmul_rn(v.z, w.z); v.w = __fmul_rn(v.w, w.w);
            }
            inner.x = __fadd_rn(inner.x, v.x);
            inner.y = __fadd_rn(inner.y, v.y);
            inner.z = __fadd_rn(inner.z, v.z);
            inner.w = __fadd_rn(inner.w, v.w);
            float4 cs;
            cs.x = __fadd_rn(C.x, inner.x); cs.y = __fadd_rn(C.y, inner.y);
            cs.z = __fadd_rn(C.z, inner.z); cs.w = __fadd_rn(C.w, inner.w);
            if (t >= 1) {
                float4 ov;
                if (t >= 3) {
                    ov.x = __fsub_rn(cs.x, h3.x); ov.y = __fsub_rn(cs.y, h3.y);
                    ov.z = __fsub_rn(cs.z, h3.z); ov.w = __fsub_rn(cs.w, h3.w);
                } else {
                    ov = cs;
                }
                po[(t - 1) * 64] = ov;
            }
            h3 = h2; h2 = h1; h1 = cs;
        }
        if (kb == 15) {
            float4 ov;
            ov.x = __fsub_rn(h1.x, h3.x); ov.y = __fsub_rn(h1.y, h3.y);
            ov.z = __fsub_rn(h1.z, h3.z); ov.w = __fsub_rn(h1.w, h3.w);
            po[(LH - 1) * 64] = ov;
        }
    }
}

// ---------------------------------------------------------------------------
// Kernel 2 (fused): horizontal scan + diff + covariance solve.
// Block = one (b, row); transposed stride-17 smem staging; thread = pixel.
// ---------------------------------------------------------------------------
__global__ void __launch_bounds__(256) gf_hsolve()
{
    int y = blockIdx.x & 255;
    int b = blockIdx.x >> 8;
    int tid = threadIdx.x;
    int wid = tid >> 5;
    int lane = tid & 31;
    int half = (lane >> 4) & 1;
    int hw = tid >> 4;          // half-warp id 0..15
    int k = lane & 15;          // 16-col block index
    int hb = half << 4;

    __shared__ float smbox[NPL][272];   // [plane][j*17 + k]

    #pragma unroll
    for (int pb = 0; pb < 2; pb++) {
        if (pb == 1 && wid > 2) break;       // whole warps 3..7 skip pass 2
        int praw = pb * 16 + hw;
        int plane = praw < NPL ? praw : NPL - 1;   // dummy half-warp clamps
        const float4* rv = (const float4*)(g_box +
            ((size_t)b * NPL + plane) * PL + (size_t)y * LW) + k * 4;
        float4 a0 = rv[0], a1 = rv[1], a2 = rv[2], a3 = rv[3];
        float cs[16] = {a0.x, a0.y, a0.z, a0.w,
                        a1.x, a1.y, a1.z, a1.w,
                        a2.x, a2.y, a2.z, a2.w,
                        a3.x, a3.y, a3.z, a3.w};
        #pragma unroll
        for (int j = 1; j < 16; j++) cs[j] = __fadd_rn(cs[j - 1], cs[j]);

        float T = cs[15];
        float carry = 0.f;
        #pragma unroll
        for (int i = 0; i < 16; i++) {
            float Ti = __shfl_sync(0xFFFFFFFFu, T, hb | i);
            if (i < k) carry = __fadd_rn(carry, Ti);   // serial fold order
        }
        #pragma unroll
        for (int j = 0; j < 16; j++) cs[j] = __fadd_rn(carry, cs[j]);

        float csp14 = __shfl_sync(0xFFFFFFFFu, cs[14], hb | ((k - 1) & 15));
        float csp15 = __shfl_sync(0xFFFFFFFFu, cs[15], hb | ((k - 1) & 15));
        float csn0  = __shfl_sync(0xFFFFFFFFu, cs[0],  hb | ((k + 1) & 15));

        float o[16];
        if (k == 0) { o[0] = cs[1]; o[1] = cs[2]; }
        else {
            o[0] = __fsub_rn(cs[1], csp14);
            o[1] = __fsub_rn(cs[2], csp15);
        }
        #pragma unroll
        for (int j = 2; j < 15; j++) o[j] = __fsub_rn(cs[j + 1], cs[j - 2]);
        o[15] = (k == 15) ? __fsub_rn(cs[15], cs[13])
                          : __fsub_rn(csn0, cs[13]);

        if (praw < NPL) {
            #pragma unroll
            for (int j = 0; j < 16; j++) smbox[plane][j * 17 + k] = o[j];
        }
    }
    __syncthreads();

    // ---- solve for pixel (y, x = tid) ----
    int x = tid;
    int loc = (x & 15) * 17 + (x >> 4);

    int y0 = max(0, y - 1), y1 = min(LH - 1, y + 1);
    int x0 = max(0, x - 1), x1 = min(LW - 1, x + 1);
    float n = (float)((y1 - y0 + 1) * (x1 - x0 + 1));

    float mx[3], my[3];
    #pragma unroll
    for (int c = 0; c < 3; c++) mx[c] = __fdiv_rn(smbox[c][loc], n);
    #pragma unroll
    for (int c = 0; c < 3; c++) my[c] = __fdiv_rn(smbox[3 + c][loc], n);

    float v[6];
    {
        const int i1[6] = {0, 0, 0, 1, 1, 2};
        const int i2[6] = {0, 1, 2, 1, 2, 2};
        #pragma unroll
        for (int kk = 0; kk < 6; kk++) {
            float d = __fdiv_rn(smbox[6 + kk][loc], n);
            float mm = __fmul_rn(mx[i1[kk]], mx[i2[kk]]);
            v[kk] = __fadd_rn(__fsub_rn(d, mm), EPSV);
        }
    }

    float c0 = __fsub_rn(__fmul_rn(v[3], v[5]), __fmul_rn(v[4], v[4]));
    float c1 = __fsub_rn(__fmul_rn(v[4], v[2]), __fmul_rn(v[1], v[5]));
    float c2 = __fsub_rn(__fmul_rn(v[1], v[4]), __fmul_rn(v[3], v[2]));
    float c3 = __fsub_rn(__fmul_rn(v[0], v[5]), __fmul_rn(v[2], v[2]));
    float c4 = __fsub_rn(__fmul_rn(v[2], v[1]), __fmul_rn(v[0], v[4]));
    float c5 = __fsub_rn(__fmul_rn(v[0], v[3]), __fmul_rn(v[1], v[1]));

    float det = __fadd_rn(__fadd_rn(__fmul_rn(c0, v[0]), __fmul_rn(c1, v[1])),
                          __fmul_rn(c2, v[2]));
    c0 = __fdiv_rn(c0, det);
    c1 = __fdiv_rn(c1, det);
    c2 = __fdiv_rn(c2, det);
    c3 = __fdiv_rn(c3, det);
    c4 = __fdiv_rn(c4, det);
    c5 = __fdiv_rn(c5, det);

    float4* o4 = (float4*)(g_ab2 + ((size_t)b * PL + (size_t)y * LW + x) * 12);

    #pragma unroll
    for (int i = 0; i < 3; i++) {
        float cov[3];
        #pragma unroll
        for (int c = 0; c < 3; c++) {
            float d = __fdiv_rn(smbox[12 + i * 3 + c][loc], n);
            cov[c] = __fsub_rn(d, __fmul_rn(mx[c], my[i]));
        }
        float A0 = __fadd_rn(__fadd_rn(__fmul_rn(c0, cov[0]), __fmul_rn(c1, cov[1])),
                             __fmul_rn(c2, cov[2]));
        float A1 = __fadd_rn(__fadd_rn(__fmul_rn(c1, cov[0]), __fmul_rn(c3, cov[1])),
                             __fmul_rn(c4, cov[2]));
        float A2 = __fadd_rn(__fadd_rn(__fmul_rn(c2, cov[0]), __fmul_rn(c4, cov[1])),
                             __fmul_rn(c5, cov[2]));
        float s = __fadd_rn(__fadd_rn(__fmul_rn(A0, mx[0]), __fmul_rn(A1, mx[1])),
                            __fmul_rn(A2, mx[2]));
        float bb = __fsub_rn(my[i], s);
        o4[i] = make_float4(A0, A1, A2, bb);
    }
}

// ---------------------------------------------------------------------------
// Kernel 3: bilinear upsample + apply. Block = one output row (b, y).
// Interior threads use compile-time dyadic x-weights (bit-identical).
// NO occupancy forcing (R15's (256,4) caused spills).
// ---------------------------------------------------------------------------
__global__ void __launch_bounds__(256) gf_apply(
    const float* __restrict__ hrx,
    float* __restrict__ out)
{
    int y = blockIdx.x & (HH - 1);
    int b = blockIdx.x >> 10;
    int t = threadIdx.x;               // lr column / output group

    __shared__ float smrow[256 * SMSTRIDE];   // 20 KB

    float fy = (y + 0.5f) * 0.25f - 0.5f;
    fy = fminf(fmaxf(fy, 0.0f), (float)(LH - 1));
    int iy0 = (int)fy;
    float wy = fy - (float)iy0;
    int iy1 = min(iy0 + 1, LH - 1);
    float wy0 = 1.0f - wy, wy1 = wy;

    // ---- Phase 1: y-lerp column t into smem ----
    {
        const float4* ab = (const float4*)g_ab2 + (size_t)b * PL * 3;
        const float4* top = ab + ((size_t)iy0 * LW + t) * 3;
        const float4* bot = ab + ((size_t)iy1 * LW + t) * 3;
        float4* dst = (float4*)(smrow + t * SMSTRIDE);
        #pragma unroll
        for (int q = 0; q < 3; q++) {
            float4 tt = top[q], bo = bot[q];
            float4 r;
            r.x = __fadd_rn(__fmul_rn(tt.x, wy0), __fmul_rn(bo.x, wy1));
            r.y = __fadd_rn(__fmul_rn(tt.y, wy0), __fmul_rn(bo.y, wy1));
            r.z = __fadd_rn(__fmul_rn(tt.z, wy0), __fmul_rn(bo.z, wy1));
            r.w = __fadd_rn(__fmul_rn(tt.w, wy0), __fmul_rn(bo.w, wy1));
            dst[q] = r;
        }
    }
    __syncthreads();

    // ---- Phase 2: x-lerp + apply for x = 4t..4t+3 ----
    const float4* pa = (const float4*)(smrow + max(t - 1, 0) * SMSTRIDE);
    const float4* pb = (const float4*)(smrow + t * SMSTRIDE);
    const float4* pc = (const float4*)(smrow + min(t + 1, LW - 1) * SMSTRIDE);

    size_t hbase = (((size_t)b * 3) * HH + y) * HW + ((size_t)t << 2);
    const size_t hpl = (size_t)HH * HW;
    float4 hq0 = *(const float4*)(hrx + hbase);
    float4 hq1 = *(const float4*)(hrx + hbase + hpl);
    float4 hq2 = *(const float4*)(hrx + hbase + 2 * hpl);
    float hx0[4] = {hq0.x, hq0.y, hq0.z, hq0.w};
    float hx1[4] = {hq1.x, hq1.y, hq1.z, hq1.w};
    float hx2[4] = {hq2.x, hq2.y, hq2.z, hq2.w};

    float* outp = out + hbase;

    if (t > 0 && t < LW - 1) {
        // interior: fixed dyadic weights, fixed A/B/C pattern (bit-identical)
        #pragma unroll
        for (int q = 0; q < 3; q++) {
            float4 A = pa[q], B = pb[q], C = pc[q];
            float4 vd[4];
            #define XLERP(dst, l, r, W0, W1)                                   \
                dst.x = __fadd_rn(__fmul_rn(l.x, W0), __fmul_rn(r.x, W1));     \
                dst.y = __fadd_rn(__fmul_rn(l.y, W0), __fmul_rn(r.y, W1));     \
                dst.z = __fadd_rn(__fmul_rn(l.z, W0), __fmul_rn(r.z, W1));     \
                dst.w = __fadd_rn(__fmul_rn(l.w, W0), __fmul_rn(r.w, W1));
            XLERP(vd[0], A, B, 0.375f, 0.625f)
            XLERP(vd[1], A, B, 0.125f, 0.875f)
            XLERP(vd[2], B, C, 0.875f, 0.125f)
            XLERP(vd[3], B, C, 0.625f, 0.375f)
            #undef XLERP
            float o[4];
            #pragma unroll
            for (int d = 0; d < 4; d++) {
                float s = __fadd_rn(__fadd_rn(__fmul_rn(vd[d].x, hx0[d]),
                                              __fmul_rn(vd[d].y, hx1[d])),
                                    __fmul_rn(vd[d].z, hx2[d]));
                o[d] = __fadd_rn(s, vd[d].w);
            }
            *(float4*)(outp + q * hpl) = make_float4(o[0], o[1], o[2], o[3]);
        }
    } else {
        // edge: general clamped path (unchanged arithmetic)
        float w0[4], w1[4];
        int s0[4], s1[4];
        #pragma unroll
        for (int d = 0; d < 4; d++) {
            float fx = ((float)(4 * t + d) + 0.5f) * 0.25f - 0.5f;
            fx = fminf(fmaxf(fx, 0.0f), (float)(LW - 1));
            int ix0 = (int)fx;
            float wx = fx - (float)ix0;
            int ix1 = min(ix0 + 1, LW - 1);
            w1[d] = wx;
            w0[d] = 1.0f - wx;
            s0[d] = ix0 - t + 1;
            s1[d] = ix1 - t + 1;
        }
        #pragma unroll
        for (int q = 0; q < 3; q++) {
            float4 A = pa[q], B = pb[q], C = pc[q];
            float o[4];
            #pragma unroll
            for (int d = 0; d < 4; d++) {
                float4 l = (s0[d] == 0) ? A : B;
                float4 r = (s1[d] == 2) ? C : B;
                float v0 = __fadd_rn(__fmul_rn(l.x, w0[d]), __fmul_rn(r.x, w1[d]));
                float v1 = __fadd_rn(__fmul_rn(l.y, w0[d]), __fmul_rn(r.y, w1[d]));
                float v2 = __fadd_rn(__fmul_rn(l.z, w0[d]), __fmul_rn(r.z, w1[d]));
                float v3 = __fadd_rn(__fmul_rn(l.w, w0[d]), __fmul_rn(r.w, w1[d]));
                float s = __fadd_rn(__fadd_rn(__fmul_rn(v0, hx0[d]),
                                              __fmul_rn(v1, hx1[d])),
                                    __fmul_rn(v2, hx2[d]));
                o[d] = __fadd_rn(s, v3);
            }
            *(float4*)(outp + q * hpl) = make_float4(o[0], o[1], o[2], o[3]);
        }
    }
}

extern "C" void kernel_launch(void* const* d_in, const int* in_sizes, int n_in,
                              void* d_out, int out_size)
{
    const float* lrx = (const float*)d_in[0];
    const float* lry = (const float*)d_in[1];
    const float* hrx = (const float*)d_in[2];
    float* out = (float*)d_out;

    gf_box_v<<<NB * NPL * 4, 256>>>(lrx, lry);       // 672 blocks
    gf_hsolve<<<NB * LH, 256>>>();                   // 2048 blocks
    gf_apply<<<NB * HH, 256>>>(hrx, out);            // 8192 blocks
}